// round 4
// baseline (speedup 1.0000x reference)
#include <cuda_runtime.h>

#define B  8
#define L  8192
#define D  768
#define NE 128
#define P  8128
#define NPAIR (B * P)

#define KC   32
#define PAD  34
#define NBLK 128
#define NTHR 256

// ---- device scratch (no allocations allowed) ----
__device__ float  g_emb[B * NE * D];    // 3 MB
__device__ float  g_norm[B * NE];
__device__ float  g_sim[B * NE * NE];   // 512 KB
__device__ float2 g_part[NBLK];         // per-tile (sum, sumsq)
__device__ unsigned g_bar_cnt[2];       // zero-init; returns to 0 each use
__device__ volatile unsigned g_bar_flag[2];

// Replay-safe grid barrier: each block reads the flag BEFORE arriving, so
// the flip (by the last arriver) is unambiguous regardless of the parity
// left over from the previous graph replay.
__device__ __forceinline__ void grid_bar(int id) {
    __syncthreads();
    if (threadIdx.x == 0) {
        unsigned start = g_bar_flag[id];
        __threadfence();
        unsigned old = atomicAdd(&g_bar_cnt[id], 1u);
        if (old == NBLK - 1u) {
            g_bar_cnt[id] = 0u;
            __threadfence();
            g_bar_flag[id] = start ^ 1u;
        } else {
            while (g_bar_flag[id] == start) { }
        }
        __threadfence();
    }
    __syncthreads();
}

__device__ __forceinline__ void f4acc(float4& a, const float4 v) {
    a.x += v.x; a.y += v.y; a.z += v.z; a.w += v.w;
}

__global__ void __launch_bounds__(NTHR, 1)
k_fused(const float* __restrict__ x,
        const int*   __restrict__ starts,
        const int*   __restrict__ lengths,
        const int*   __restrict__ hts,
        const float* __restrict__ thr_p,
        const float* __restrict__ W1,
        const float* __restrict__ b1,
        const float* __restrict__ W2,
        const float* __restrict__ b2,
        float*       __restrict__ out) {
    int tid  = threadIdx.x;
    int bid  = blockIdx.x;
    int lane = tid & 31;
    int warp = tid >> 5;

    __shared__ float As[KC][PAD];
    __shared__ float Bs[KC][PAD];
    __shared__ float wpart[8][6];
    __shared__ float ws[8], wq[8];
    __shared__ float4 sw1[32], sb1[32], sw2[64];
    __shared__ float  smisc[2 + B];     // [0..1]=b2, [2..9]=alpha per batch

    // ================= Phase 1: span mean pool + norms =================
    // 8 spans per block; 192 threads active (6 full warps), 8-deep MLP.
    #pragma unroll 1
    for (int sp = 0; sp < 8; ++sp) {
        int be = bid * 8 + sp;
        if (tid < 192) {
            int b   = be >> 7;
            int s   = starts[be];
            int len = lengths[be];
            const float* xp = x + ((size_t)b * L + s) * D;

            float4 z = make_float4(0.f, 0.f, 0.f, 0.f);
            float4 a0 = z, a1 = z, a2 = z, a3 = z;
            int t = 0;
            for (; t + 8 <= len; t += 8) {
                float4 v0 = ((const float4*)(xp + (size_t)(t+0) * D))[tid];
                float4 v1 = ((const float4*)(xp + (size_t)(t+1) * D))[tid];
                float4 v2 = ((const float4*)(xp + (size_t)(t+2) * D))[tid];
                float4 v3 = ((const float4*)(xp + (size_t)(t+3) * D))[tid];
                float4 v4 = ((const float4*)(xp + (size_t)(t+4) * D))[tid];
                float4 v5 = ((const float4*)(xp + (size_t)(t+5) * D))[tid];
                float4 v6 = ((const float4*)(xp + (size_t)(t+6) * D))[tid];
                float4 v7 = ((const float4*)(xp + (size_t)(t+7) * D))[tid];
                f4acc(a0, v0); f4acc(a1, v1); f4acc(a2, v2); f4acc(a3, v3);
                f4acc(a0, v4); f4acc(a1, v5); f4acc(a2, v6); f4acc(a3, v7);
            }
            for (; t + 4 <= len; t += 4) {
                float4 v0 = ((const float4*)(xp + (size_t)(t+0) * D))[tid];
                float4 v1 = ((const float4*)(xp + (size_t)(t+1) * D))[tid];
                float4 v2 = ((const float4*)(xp + (size_t)(t+2) * D))[tid];
                float4 v3 = ((const float4*)(xp + (size_t)(t+3) * D))[tid];
                f4acc(a0, v0); f4acc(a1, v1); f4acc(a2, v2); f4acc(a3, v3);
            }
            for (; t < len; ++t) {
                float4 v = ((const float4*)(xp + (size_t)t * D))[tid];
                f4acc(a0, v);
            }
            float4 acc;
            acc.x = (a0.x + a1.x) + (a2.x + a3.x);
            acc.y = (a0.y + a1.y) + (a2.y + a3.y);
            acc.z = (a0.z + a1.z) + (a2.z + a3.z);
            acc.w = (a0.w + a1.w) + (a2.w + a3.w);
            float inv = 1.0f / (float)len;
            acc.x *= inv; acc.y *= inv; acc.z *= inv; acc.w *= inv;
            ((float4*)(g_emb + (size_t)be * D))[tid] = acc;

            float nsq = acc.x*acc.x + acc.y*acc.y + acc.z*acc.z + acc.w*acc.w;
            #pragma unroll
            for (int o = 16; o; o >>= 1) nsq += __shfl_xor_sync(0xffffffffu, nsq, o);
            if (lane == 0) wpart[sp][warp] = nsq;
        }
    }
    __syncthreads();
    if (tid < 8) {
        float tt = 0.f;
        #pragma unroll
        for (int w = 0; w < 6; ++w) tt += wpart[tid][w];
        g_norm[bid * 8 + tid] = sqrtf(tt);
    }

    grid_bar(0);

    // ========== Phase 2: tiled Gram + cosine + per-tile stats ==========
    // Block bid handles one 32x32 tile: b = bid>>4, ti = (bid>>2)&3, tj = bid&3.
    {
        int b  = bid >> 4;
        int ti = (bid >> 2) & 3;
        int tj = bid & 3;
        int tx = tid & 15;
        int ty = tid >> 4;

        const float* Ea = g_emb + ((size_t)(b * NE + ti * 32)) * D;
        const float* Eb = g_emb + ((size_t)(b * NE + tj * 32)) * D;

        int lr = tid >> 3;
        int lc = (tid & 7) * 4;

        float acc00 = 0.f, acc01 = 0.f, acc10 = 0.f, acc11 = 0.f;

        for (int kc = 0; kc < D; kc += KC) {
            float4 av = *(const float4*)(Ea + (size_t)lr * D + kc + lc);
            float4 bv = *(const float4*)(Eb + (size_t)lr * D + kc + lc);
            __syncthreads();
            As[lc+0][lr] = av.x; As[lc+1][lr] = av.y;
            As[lc+2][lr] = av.z; As[lc+3][lr] = av.w;
            Bs[lc+0][lr] = bv.x; Bs[lc+1][lr] = bv.y;
            Bs[lc+2][lr] = bv.z; Bs[lc+3][lr] = bv.w;
            __syncthreads();
            #pragma unroll
            for (int k = 0; k < KC; ++k) {
                float2 a  = *(const float2*)&As[k][ty * 2];
                float2 bb = *(const float2*)&Bs[k][tx * 2];
                acc00 = fmaf(a.x, bb.x, acc00);
                acc01 = fmaf(a.x, bb.y, acc01);
                acc10 = fmaf(a.y, bb.x, acc10);
                acc11 = fmaf(a.y, bb.y, acc11);
            }
        }

        int i = ti * 32 + ty * 2;
        int j = tj * 32 + tx * 2;
        float ni0 = g_norm[b * NE + i],     ni1 = g_norm[b * NE + i + 1];
        float nj0 = g_norm[b * NE + j],     nj1 = g_norm[b * NE + j + 1];
        float v00 = acc00 / fmaxf(ni0 * nj0, 1e-8f);
        float v01 = acc01 / fmaxf(ni0 * nj1, 1e-8f);
        float v10 = acc10 / fmaxf(ni1 * nj0, 1e-8f);
        float v11 = acc11 / fmaxf(ni1 * nj1, 1e-8f);
        float* r0 = g_sim + ((size_t)(b * NE + i)) * NE + j;
        ((float2*)r0)[0]        = make_float2(v00, v01);
        ((float2*)(r0 + NE))[0] = make_float2(v10, v11);

        float s = (v00 + v01) + (v10 + v11);
        float q = (v00*v00 + v01*v01) + (v10*v10 + v11*v11);
        #pragma unroll
        for (int o = 16; o; o >>= 1) {
            s += __shfl_xor_sync(0xffffffffu, s, o);
            q += __shfl_xor_sync(0xffffffffu, q, o);
        }
        if (lane == 0) { ws[warp] = s; wq[warp] = q; }
        __syncthreads();
        if (tid == 0) {
            float S = ((ws[0]+ws[1]) + (ws[2]+ws[3])) + ((ws[4]+ws[5]) + (ws[6]+ws[7]));
            float Q = ((wq[0]+wq[1]) + (wq[2]+wq[3])) + ((wq[4]+wq[5]) + (wq[6]+wq[7]));
            g_part[bid] = make_float2(S, Q);
        }
    }

    grid_bar(1);

    // ============ Phase 3: alphas + pair gather + MLP ============
    // Every block redundantly computes the 8 alphas (fixed-order, deterministic).
    if (tid < 32)        sw1[tid]        = ((const float4*)W1)[tid];
    else if (tid < 64)   sb1[tid - 32]   = ((const float4*)b1)[tid - 32];
    else if (tid < 128)  sw2[tid - 64]   = ((const float4*)W2)[tid - 64];
    else if (tid < 130)  smisc[tid - 128] = b2[tid - 128];
    else if (tid < 130 + B) {
        int bb = tid - 130;
        float S = 0.f, Q = 0.f;
        #pragma unroll
        for (int t = 0; t < 16; ++t) {
            float2 pp = g_part[bb * 16 + t];
            S += pp.x; Q += pp.y;
        }
        const float N = (float)(NE * NE);
        float var = (Q - S * S / N) / (N - 1.0f);
        smisc[2 + bb] = 1.0f / (sqrtf(fmaxf(var, 0.0f)) + 1e-5f);
    }
    __syncthreads();

    float thr = thr_p[0];
    int g0 = bid * NTHR + tid;          // 0..32767
    int p0 = g0;
    int p1 = g0 + NBLK * NTHR;          // 32768..65535
    bool has1 = (p1 < NPAIR);

    int  b0  = p0 / P;
    int2 ij0 = ((const int2*)hts)[p0];
    float sv0 = (g_sim[((size_t)(b0 * NE + ij0.x)) * NE + ij0.y] - thr) * smisc[2 + b0];

    int  p1c = has1 ? p1 : p0;
    int  b1i = p1c / P;
    int2 ij1 = ((const int2*)hts)[p1c];
    float sv1 = (g_sim[((size_t)(b1i * NE + ij1.x)) * NE + ij1.y] - thr) * smisc[2 + b1i];

    float l00 = 0.f, l01 = 0.f, l10 = 0.f, l11 = 0.f;
    #pragma unroll
    for (int kk = 0; kk < 32; ++kk) {
        float4 w1v = sw1[kk];
        float4 b1v = sb1[kk];
        float4 w2a = sw2[2 * kk];
        float4 w2b = sw2[2 * kk + 1];
        float h0 = fmaxf(fmaf(sv0, w1v.x, b1v.x), 0.0f);
        float h1 = fmaxf(fmaf(sv0, w1v.y, b1v.y), 0.0f);
        float h2 = fmaxf(fmaf(sv0, w1v.z, b1v.z), 0.0f);
        float h3 = fmaxf(fmaf(sv0, w1v.w, b1v.w), 0.0f);
        l00 = fmaf(h0, w2a.x, l00);  l01 = fmaf(h0, w2a.y, l01);
        l00 = fmaf(h1, w2a.z, l00);  l01 = fmaf(h1, w2a.w, l01);
        l00 = fmaf(h2, w2b.x, l00);  l01 = fmaf(h2, w2b.y, l01);
        l00 = fmaf(h3, w2b.z, l00);  l01 = fmaf(h3, w2b.w, l01);
        float g0h = fmaxf(fmaf(sv1, w1v.x, b1v.x), 0.0f);
        float g1h = fmaxf(fmaf(sv1, w1v.y, b1v.y), 0.0f);
        float g2h = fmaxf(fmaf(sv1, w1v.z, b1v.z), 0.0f);
        float g3h = fmaxf(fmaf(sv1, w1v.w, b1v.w), 0.0f);
        l10 = fmaf(g0h, w2a.x, l10);  l11 = fmaf(g0h, w2a.y, l11);
        l10 = fmaf(g1h, w2a.z, l10);  l11 = fmaf(g1h, w2a.w, l11);
        l10 = fmaf(g2h, w2b.x, l10);  l11 = fmaf(g2h, w2b.y, l11);
        l10 = fmaf(g3h, w2b.z, l10);  l11 = fmaf(g3h, w2b.w, l11);
    }
    ((float2*)out)[p0] = make_float2(l00 + smisc[0], l01 + smisc[1]);
    if (has1)
        ((float2*)out)[p1] = make_float2(l10 + smisc[0], l11 + smisc[1]);
}

// ------------------------------------------------------------------
extern "C" void kernel_launch(void* const* d_in, const int* in_sizes, int n_in,
                              void* d_out, int out_size) {
    const float* x       = (const float*)d_in[0];
    const int*   starts  = (const int*)  d_in[1];
    const int*   lengths = (const int*)  d_in[2];
    const int*   hts     = (const int*)  d_in[3];
    const float* thr     = (const float*)d_in[4];
    const float* W1      = (const float*)d_in[5];
    const float* b1      = (const float*)d_in[6];
    const float* W2      = (const float*)d_in[7];
    const float* b2      = (const float*)d_in[8];
    float*       out     = (float*)d_out;

    k_fused<<<NBLK, NTHR>>>(x, starts, lengths, hts, thr, W1, b1, W2, b2, out);
}

// round 5
// speedup vs baseline: 1.2901x; 1.2901x over previous
#include <cuda_runtime.h>

#define B  8
#define L  8192
#define D  768
#define NE 128
#define P  8128
#define NPAIR (B * P)

#define KC   32
#define PADK 36      // smem row stride (floats), 16B-aligned rows
#define NBLK 128
#define NTHR 256

// ---- device scratch (no allocations allowed) ----
__device__ float  g_emb[B * NE * D];    // 3 MB
__device__ float  g_norm[B * NE];
__device__ float  g_sim[B * NE * NE];   // 512 KB
__device__ float2 g_part[NBLK];         // per-tile (sum, sumsq)
__device__ unsigned g_bar_cnt[2];
__device__ volatile unsigned g_bar_flag[2];

// Replay-safe grid barrier (flag read BEFORE arrival -> parity-agnostic).
__device__ __forceinline__ void grid_bar(int id) {
    __syncthreads();
    if (threadIdx.x == 0) {
        unsigned start = g_bar_flag[id];
        __threadfence();
        unsigned old = atomicAdd(&g_bar_cnt[id], 1u);
        if (old == NBLK - 1u) {
            g_bar_cnt[id] = 0u;
            __threadfence();
            g_bar_flag[id] = start ^ 1u;
        } else {
            while (g_bar_flag[id] == start) { }
        }
        __threadfence();
    }
    __syncthreads();
}

__device__ __forceinline__ void f4acc(float4& a, const float4 v) {
    a.x += v.x; a.y += v.y; a.z += v.z; a.w += v.w;
}

__global__ void __launch_bounds__(NTHR, 1)
k_fused(const float* __restrict__ x,
        const int*   __restrict__ starts,
        const int*   __restrict__ lengths,
        const int*   __restrict__ hts,
        const float* __restrict__ thr_p,
        const float* __restrict__ W1,
        const float* __restrict__ b1,
        const float* __restrict__ W2,
        const float* __restrict__ b2,
        float*       __restrict__ out) {
    int tid  = threadIdx.x;
    int bid  = blockIdx.x;
    int lane = tid & 31;
    int warp = tid >> 5;

    // Phase-2 k-split tiles: 4 groups x (A,B) 32k x 32rows, padded.
    __shared__ float As[4][KC][PADK];   // 18.4 KB
    __shared__ float Bs[4][KC][PADK];   // 18.4 KB
    __shared__ float ws[8], wq[8];
    __shared__ float4 sw1[32], sb1[32], sw2[64];
    __shared__ float  smisc[2 + B];     // [0..1]=b2, [2..9]=alpha

    // ================= Phase 1: one warp per span =================
    {
        int sp  = bid * 8 + warp;        // 0..1023
        int b   = sp >> 7;
        int s   = starts[sp];
        int len = lengths[sp];
        const float4* xp = (const float4*)(x + ((size_t)b * L + s) * D);

        float4 z = make_float4(0.f, 0.f, 0.f, 0.f);
        float4 acc[6] = { z, z, z, z, z, z };
        int t = 0;
        for (; t + 2 <= len; t += 2) {
            float4 v0[6], v1[6];
            #pragma unroll
            for (int c = 0; c < 6; ++c) v0[c] = xp[(size_t)(t+0) * 192 + lane + c * 32];
            #pragma unroll
            for (int c = 0; c < 6; ++c) v1[c] = xp[(size_t)(t+1) * 192 + lane + c * 32];
            #pragma unroll
            for (int c = 0; c < 6; ++c) { f4acc(acc[c], v0[c]); f4acc(acc[c], v1[c]); }
        }
        if (t < len) {
            #pragma unroll
            for (int c = 0; c < 6; ++c) f4acc(acc[c], xp[(size_t)t * 192 + lane + c * 32]);
        }
        float inv = 1.0f / (float)len;
        float nsq = 0.f;
        float4* ep = (float4*)(g_emb + (size_t)sp * D);
        #pragma unroll
        for (int c = 0; c < 6; ++c) {
            acc[c].x *= inv; acc[c].y *= inv; acc[c].z *= inv; acc[c].w *= inv;
            ep[lane + c * 32] = acc[c];
            nsq += acc[c].x*acc[c].x + acc[c].y*acc[c].y
                 + acc[c].z*acc[c].z + acc[c].w*acc[c].w;
        }
        #pragma unroll
        for (int o = 16; o; o >>= 1) nsq += __shfl_xor_sync(0xffffffffu, nsq, o);
        if (lane == 0) g_norm[sp] = sqrtf(nsq);
    }

    grid_bar(0);

    // ===== Phase 2: Gram tile 32x32, 4x4 micro, k-split-4 =====
    // bid -> (b, ti, tj); group g = tid>>6 handles k in [g*192, g*192+192).
    {
        int b   = bid >> 4;
        int ti  = (bid >> 2) & 3;
        int tj  = bid & 3;
        int g   = tid >> 6;          // 0..3
        int t64 = tid & 63;
        int tx  = t64 & 7;           // j/4
        int ty  = t64 >> 3;          // i/4

        const float* Ea = g_emb + ((size_t)(b * NE + ti * 32)) * D;
        const float* Eb = g_emb + ((size_t)(b * NE + tj * 32)) * D;

        int lr = t64 >> 1;           // row 0..31
        int lh = (t64 & 1) * 16;     // k-half within 32-chunk

        float a00=0,a01=0,a02=0,a03=0, a10=0,a11=0,a12=0,a13=0;
        float a20=0,a21=0,a22=0,a23=0, a30=0,a31=0,a32=0,a33=0;

        #pragma unroll 1
        for (int s6 = 0; s6 < 6; ++s6) {
            int kb = g * 192 + s6 * KC;
            float4 av[4], bv[4];
            #pragma unroll
            for (int q = 0; q < 4; ++q) {
                av[q] = *(const float4*)(Ea + (size_t)lr * D + kb + lh + q * 4);
                bv[q] = *(const float4*)(Eb + (size_t)lr * D + kb + lh + q * 4);
            }
            __syncthreads();
            #pragma unroll
            for (int q = 0; q < 4; ++q) {
                int kk = lh + q * 4;
                As[g][kk+0][lr] = av[q].x; As[g][kk+1][lr] = av[q].y;
                As[g][kk+2][lr] = av[q].z; As[g][kk+3][lr] = av[q].w;
                Bs[g][kk+0][lr] = bv[q].x; Bs[g][kk+1][lr] = bv[q].y;
                Bs[g][kk+2][lr] = bv[q].z; Bs[g][kk+3][lr] = bv[q].w;
            }
            __syncthreads();
            #pragma unroll
            for (int k = 0; k < KC; ++k) {
                float4 a = *(const float4*)&As[g][k][ty * 4];
                float4 bb = *(const float4*)&Bs[g][k][tx * 4];
                a00 = fmaf(a.x, bb.x, a00); a01 = fmaf(a.x, bb.y, a01);
                a02 = fmaf(a.x, bb.z, a02); a03 = fmaf(a.x, bb.w, a03);
                a10 = fmaf(a.y, bb.x, a10); a11 = fmaf(a.y, bb.y, a11);
                a12 = fmaf(a.y, bb.z, a12); a13 = fmaf(a.y, bb.w, a13);
                a20 = fmaf(a.z, bb.x, a20); a21 = fmaf(a.z, bb.y, a21);
                a22 = fmaf(a.z, bb.z, a22); a23 = fmaf(a.z, bb.w, a23);
                a30 = fmaf(a.w, bb.x, a30); a31 = fmaf(a.w, bb.y, a31);
                a32 = fmaf(a.w, bb.z, a32); a33 = fmaf(a.w, bb.w, a33);
            }
        }

        // combine 4 k-partials deterministically via smem (reuse As/Bs space)
        float* red = &As[0][0][0];              // 4 * 1024 floats = 16 KB
        __syncthreads();
        {
            int ob = (ty * 4) * 32 + tx * 4;    // output base (i*32 + j)
            float* rg = red + g * 1024;
            rg[ob +  0] = a00; rg[ob +  1] = a01; rg[ob +  2] = a02; rg[ob +  3] = a03;
            rg[ob + 32] = a10; rg[ob + 33] = a11; rg[ob + 34] = a12; rg[ob + 35] = a13;
            rg[ob + 64] = a20; rg[ob + 65] = a21; rg[ob + 66] = a22; rg[ob + 67] = a23;
            rg[ob + 96] = a30; rg[ob + 97] = a31; rg[ob + 98] = a32; rg[ob + 99] = a33;
        }
        __syncthreads();

        // each thread finalizes 4 consecutive outputs (one float4 row chunk)
        int o  = tid * 4;
        int i  = o >> 5;
        int j  = o & 31;
        float v0 = ((red[o+0] + red[1024+o+0]) + (red[2048+o+0] + red[3072+o+0]));
        float v1 = ((red[o+1] + red[1024+o+1]) + (red[2048+o+1] + red[3072+o+1]));
        float v2 = ((red[o+2] + red[1024+o+2]) + (red[2048+o+2] + red[3072+o+2]));
        float v3 = ((red[o+3] + red[1024+o+3]) + (red[2048+o+3] + red[3072+o+3]));

        int gi = ti * 32 + i;
        int gj = tj * 32 + j;
        float ni = g_norm[b * NE + gi];
        float nj0 = g_norm[b * NE + gj + 0], nj1 = g_norm[b * NE + gj + 1];
        float nj2 = g_norm[b * NE + gj + 2], nj3 = g_norm[b * NE + gj + 3];
        v0 = v0 / fmaxf(ni * nj0, 1e-8f);
        v1 = v1 / fmaxf(ni * nj1, 1e-8f);
        v2 = v2 / fmaxf(ni * nj2, 1e-8f);
        v3 = v3 / fmaxf(ni * nj3, 1e-8f);
        *(float4*)(g_sim + ((size_t)(b * NE + gi)) * NE + gj) =
            make_float4(v0, v1, v2, v3);

        float s = (v0 + v1) + (v2 + v3);
        float q = (v0*v0 + v1*v1) + (v2*v2 + v3*v3);
        #pragma unroll
        for (int off = 16; off; off >>= 1) {
            s += __shfl_xor_sync(0xffffffffu, s, off);
            q += __shfl_xor_sync(0xffffffffu, q, off);
        }
        if (lane == 0) { ws[warp] = s; wq[warp] = q; }
        __syncthreads();
        if (tid == 0) {
            float S = ((ws[0]+ws[1]) + (ws[2]+ws[3])) + ((ws[4]+ws[5]) + (ws[6]+ws[7]));
            float Q = ((wq[0]+wq[1]) + (wq[2]+wq[3])) + ((wq[4]+wq[5]) + (wq[6]+wq[7]));
            g_part[bid] = make_float2(S, Q);
        }
    }

    grid_bar(1);

    // ============ Phase 3: alphas + pair gather + MLP ============
    if (tid < 32)        sw1[tid]        = ((const float4*)W1)[tid];
    else if (tid < 64)   sb1[tid - 32]   = ((const float4*)b1)[tid - 32];
    else if (tid < 128)  sw2[tid - 64]   = ((const float4*)W2)[tid - 64];
    else if (tid < 130)  smisc[tid - 128] = b2[tid - 128];
    else if (tid < 130 + B) {
        int bb = tid - 130;
        float S = 0.f, Q = 0.f;
        #pragma unroll
        for (int t = 0; t < 16; ++t) {
            float2 pp = g_part[bb * 16 + t];
            S += pp.x; Q += pp.y;
        }
        const float N = (float)(NE * NE);
        float var = (Q - S * S / N) / (N - 1.0f);
        smisc[2 + bb] = 1.0f / (sqrtf(fmaxf(var, 0.0f)) + 1e-5f);
    }
    __syncthreads();

    float thr = thr_p[0];
    int g0 = bid * NTHR + tid;          // 0..32767
    int p0 = g0;
    int p1 = g0 + NBLK * NTHR;          // 32768..65535
    bool has1 = (p1 < NPAIR);

    int  b0  = p0 / P;
    int2 ij0 = ((const int2*)hts)[p0];
    float sv0 = (g_sim[((size_t)(b0 * NE + ij0.x)) * NE + ij0.y] - thr) * smisc[2 + b0];

    int  p1c = has1 ? p1 : p0;
    int  b1i = p1c / P;
    int2 ij1 = ((const int2*)hts)[p1c];
    float sv1 = (g_sim[((size_t)(b1i * NE + ij1.x)) * NE + ij1.y] - thr) * smisc[2 + b1i];

    float l00 = 0.f, l01 = 0.f, l10 = 0.f, l11 = 0.f;
    #pragma unroll
    for (int kk = 0; kk < 32; ++kk) {
        float4 w1v = sw1[kk];
        float4 b1v = sb1[kk];
        float4 w2a = sw2[2 * kk];
        float4 w2b = sw2[2 * kk + 1];
        float h0 = fmaxf(fmaf(sv0, w1v.x, b1v.x), 0.0f);
        float h1 = fmaxf(fmaf(sv0, w1v.y, b1v.y), 0.0f);
        float h2 = fmaxf(fmaf(sv0, w1v.z, b1v.z), 0.0f);
        float h3 = fmaxf(fmaf(sv0, w1v.w, b1v.w), 0.0f);
        l00 = fmaf(h0, w2a.x, l00);  l01 = fmaf(h0, w2a.y, l01);
        l00 = fmaf(h1, w2a.z, l00);  l01 = fmaf(h1, w2a.w, l01);
        l00 = fmaf(h2, w2b.x, l00);  l01 = fmaf(h2, w2b.y, l01);
        l00 = fmaf(h3, w2b.z, l00);  l01 = fmaf(h3, w2b.w, l01);
        float e0 = fmaxf(fmaf(sv1, w1v.x, b1v.x), 0.0f);
        float e1 = fmaxf(fmaf(sv1, w1v.y, b1v.y), 0.0f);
        float e2 = fmaxf(fmaf(sv1, w1v.z, b1v.z), 0.0f);
        float e3 = fmaxf(fmaf(sv1, w1v.w, b1v.w), 0.0f);
        l10 = fmaf(e0, w2a.x, l10);  l11 = fmaf(e0, w2a.y, l11);
        l10 = fmaf(e1, w2a.z, l10);  l11 = fmaf(e1, w2a.w, l11);
        l10 = fmaf(e2, w2b.x, l10);  l11 = fmaf(e2, w2b.y, l11);
        l10 = fmaf(e3, w2b.z, l10);  l11 = fmaf(e3, w2b.w, l11);
    }
    ((float2*)out)[p0] = make_float2(l00 + smisc[0], l01 + smisc[1]);
    if (has1)
        ((float2*)out)[p1] = make_float2(l10 + smisc[0], l11 + smisc[1]);
}

// ------------------------------------------------------------------
extern "C" void kernel_launch(void* const* d_in, const int* in_sizes, int n_in,
                              void* d_out, int out_size) {
    const float* x       = (const float*)d_in[0];
    const int*   starts  = (const int*)  d_in[1];
    const int*   lengths = (const int*)  d_in[2];
    const int*   hts     = (const int*)  d_in[3];
    const float* thr     = (const float*)d_in[4];
    const float* W1      = (const float*)d_in[5];
    const float* b1      = (const float*)d_in[6];
    const float* W2      = (const float*)d_in[7];
    const float* b2      = (const float*)d_in[8];
    float*       out     = (float*)d_out;

    k_fused<<<NBLK, NTHR>>>(x, starts, lengths, hts, thr, W1, b1, W2, b2, out);
}